// round 11
// baseline (speedup 1.0000x reference)
#include <cuda_runtime.h>
#include <cstddef>

// Fixed shapes
constexpr int B = 32;
constexpr int C = 256;
constexpr int H = 64;
constexpr int HW = H * H;           // 4096 pixels
constexpr int N = 2048;             // anchors per batch
constexpr int CHUNK = 2;            // channels per CTA
constexpr int NCHUNKS = C / CHUNK;  // 128
constexpr int THREADS = 256;        // 8 warps
constexpr size_t SMEM_BYTES = (size_t)HW * CHUNK * 4;  // 32 KB -> 6 CTAs/SM

__device__ __forceinline__ float2 lerp2(float2 a, float2 b, float t) {
    return make_float2(fmaf(b.x - a.x, t, a.x),
                       fmaf(b.y - a.y, t, a.y));
}

__global__ __launch_bounds__(THREADS, 6)
void bilinear_gather_kernel(const float* __restrict__ fm,
                            const float* __restrict__ anchors,
                            float* __restrict__ out)
{
    extern __shared__ float2 s2[];   // pixel-major: s2[p] = {c0, c1}

    const int blk   = blockIdx.x;
    const int b     = blk >> 7;      // / NCHUNKS
    const int chunk = blk & 127;     // % NCHUNKS

    // ---- Stage + transpose to pixel-major (32 KB).
    // Per thread: 16 pixels, 2 coalesced scalar LDG each -> STS.64 with
    // consecutive lane addresses (conflict-free).
    {
        const float* __restrict__ src =
            fm + ((size_t)b * C + (size_t)chunk * CHUNK) * HW;
        #pragma unroll
        for (int p = threadIdx.x; p < HW; p += THREADS) {
            float2 v;
            v.x = src[p];
            v.y = src[HW + p];
            s2[p] = v;
        }
    }
    __syncthreads();

    const float2* __restrict__ anc2 =
        reinterpret_cast<const float2*>(anchors + (size_t)b * N * 2);
    float* __restrict__ outb = out + (size_t)b * N * C + (size_t)chunk * CHUNK;

    // ---- Gather: one thread per anchor, math once per anchor, 4x LDS.64.
    // 8 independent iterations -> deep LDS ILP.
    #pragma unroll
    for (int i = 0; i < N / THREADS; ++i) {
        const int n = i * THREADS + threadIdx.x;

        float2 a = anc2[n];
        float px = fminf(fmaxf(a.x * 63.0f, 0.0f), 63.0f);
        float py = fminf(fmaxf(a.y * 63.0f, 0.0f), 63.0f);

        float fx = floorf(px), fy = floorf(py);
        float cx = ceilf(px),  cy = ceilf(py);   // matches reference (rb==lt when integral)
        int xl = (int)fx, yl = (int)fy;
        int xr = (int)cx, yr = (int)cy;
        float dx = px - fx;
        float dy = py - fy;

        float2 vlt = s2[yl * H + xl];
        float2 vrt = s2[yl * H + xr];
        float2 vlb = s2[yr * H + xl];
        float2 vrb = s2[yr * H + xr];

        float2 vt = lerp2(vlt, vrt, dx);
        float2 vb = lerp2(vlb, vrb, dx);
        float2 r  = lerp2(vt, vb, dy);

        *reinterpret_cast<float2*>(outb + (size_t)n * C) = r;   // STG.64
    }
}

extern "C" void kernel_launch(void* const* d_in, const int* in_sizes, int n_in,
                              void* d_out, int out_size)
{
    const float* fm      = (const float*)d_in[0];  // (32,256,64,64) fp32
    const float* anchors = (const float*)d_in[1];  // (32,2048,2) fp32
    float* out           = (float*)d_out;          // (32,2048,256) fp32

    cudaFuncSetAttribute(bilinear_gather_kernel,
                         cudaFuncAttributeMaxDynamicSharedMemorySize,
                         (int)SMEM_BYTES);

    dim3 grid(B * NCHUNKS);   // 4096 CTAs
    dim3 block(THREADS);
    bilinear_gather_kernel<<<grid, block, SMEM_BYTES>>>(fm, anchors, out);
}

// round 12
// speedup vs baseline: 1.0425x; 1.0425x over previous
#include <cuda_runtime.h>
#include <cstddef>

// Fixed shapes
constexpr int B = 32;
constexpr int C = 256;
constexpr int H = 64;
constexpr int HW = H * H;           // 4096 pixels
constexpr int N = 2048;             // anchors per batch
constexpr int CHUNK = 4;            // channels per tile
constexpr int NCHUNKS = C / CHUNK;  // 64
constexpr int TILES = B * NCHUNKS;  // 2048 tiles total
constexpr int THREADS = 1024;       // 32 warps
constexpr int GRID = 148;           // one persistent CTA per SM (B200: 148 SMs)
constexpr int PPT = HW / THREADS;   // 4 pixels per thread per tile
constexpr size_t SMEM_BYTES = 2ull * HW * CHUNK * 4;   // 2 x 64 KB ping-pong

__device__ __forceinline__ float4 lerp4(float4 a, float4 b, float t) {
    return make_float4(fmaf(b.x - a.x, t, a.x),
                       fmaf(b.y - a.y, t, a.y),
                       fmaf(b.z - a.z, t, a.z),
                       fmaf(b.w - a.w, t, a.w));
}

__global__ __launch_bounds__(THREADS, 1)
void bilinear_gather_kernel(const float* __restrict__ fm,
                            const float* __restrict__ anchors,
                            float* __restrict__ out)
{
    extern __shared__ float4 sbuf[];   // [2][4096] pixel-major: {c0,c1,c2,c3}

    const int tid = threadIdx.x;

    // Static balanced partition of 2048 tiles over 148 CTAs (13 or 14 each).
    const int lo = (int)(((long long)blockIdx.x       * TILES) / GRID);
    const int hi = (int)(((long long)(blockIdx.x + 1) * TILES) / GRID);
    if (lo >= hi) return;

    // Register staging buffer for the in-flight tile (16 floats/thread).
    float4 v[PPT];

    // ---- Prologue: load first tile into registers (coalesced scalar LDG:
    // consecutive tid -> consecutive pixel within a channel plane).
    {
        const int t = lo;
        const float* __restrict__ src =
            fm + ((size_t)(t >> 6) * C + (size_t)(t & 63) * CHUNK) * HW;
        #pragma unroll
        for (int i = 0; i < PPT; ++i) {
            const int p = tid + i * THREADS;
            v[i].x = src[0 * HW + p];
            v[i].y = src[1 * HW + p];
            v[i].z = src[2 * HW + p];
            v[i].w = src[3 * HW + p];
        }
    }

    for (int t = lo; t < hi; ++t) {
        float4* __restrict__ buf = sbuf + ((t - lo) & 1) * HW;

        // Drain register buffer -> smem (STS.128, consecutive lanes: conflict-free).
        #pragma unroll
        for (int i = 0; i < PPT; ++i)
            buf[tid + i * THREADS] = v[i];

        // Issue LDGs for the NEXT tile now; their latency hides under the
        // gather phase below.
        if (t + 1 < hi) {
            const int tn = t + 1;
            const float* __restrict__ src =
                fm + ((size_t)(tn >> 6) * C + (size_t)(tn & 63) * CHUNK) * HW;
            #pragma unroll
            for (int i = 0; i < PPT; ++i) {
                const int p = tid + i * THREADS;
                v[i].x = src[0 * HW + p];
                v[i].y = src[1 * HW + p];
                v[i].z = src[2 * HW + p];
                v[i].w = src[3 * HW + p];
            }
        }

        __syncthreads();   // staging stores visible to all gatherers

        // ---- Gather tile t: 2 anchors per thread, 4x LDS.128 per anchor,
        // coordinate math computed once per anchor.
        {
            const int b     = t >> 6;
            const int chunk = t & 63;
            const float2* __restrict__ anc2 =
                reinterpret_cast<const float2*>(anchors + (size_t)b * N * 2);
            float* __restrict__ outb =
                out + (size_t)b * N * C + (size_t)chunk * CHUNK;

            #pragma unroll
            for (int j = 0; j < N / THREADS; ++j) {
                const int n = tid + j * THREADS;

                float2 a = anc2[n];
                float px = fminf(fmaxf(a.x * 63.0f, 0.0f), 63.0f);
                float py = fminf(fmaxf(a.y * 63.0f, 0.0f), 63.0f);

                float fx = floorf(px), fy = floorf(py);
                float cx = ceilf(px),  cy = ceilf(py);  // matches reference
                int xl = (int)fx, yl = (int)fy;
                int xr = (int)cx, yr = (int)cy;
                float dx = px - fx;
                float dy = py - fy;

                float4 vlt = buf[yl * H + xl];
                float4 vrt = buf[yl * H + xr];
                float4 vlb = buf[yr * H + xl];
                float4 vrb = buf[yr * H + xr];

                float4 vt = lerp4(vlt, vrt, dx);
                float4 vb = lerp4(vlb, vrb, dx);
                float4 r  = lerp4(vt, vb, dy);

                *reinterpret_cast<float4*>(outb + (size_t)n * C) = r;  // STG.128
            }
        }

        __syncthreads();   // gather done before this buffer is refilled (t+2)
    }
}

extern "C" void kernel_launch(void* const* d_in, const int* in_sizes, int n_in,
                              void* d_out, int out_size)
{
    const float* fm      = (const float*)d_in[0];  // (32,256,64,64) fp32
    const float* anchors = (const float*)d_in[1];  // (32,2048,2) fp32
    float* out           = (float*)d_out;          // (32,2048,256) fp32

    cudaFuncSetAttribute(bilinear_gather_kernel,
                         cudaFuncAttributeMaxDynamicSharedMemorySize,
                         (int)SMEM_BYTES);

    dim3 grid(GRID);          // 148 persistent CTAs
    dim3 block(THREADS);      // 1024 threads
    bilinear_gather_kernel<<<grid, block, SMEM_BYTES>>>(fm, anchors, out);
}

// round 13
// speedup vs baseline: 1.3320x; 1.2778x over previous
#include <cuda_runtime.h>
#include <cstddef>

// Fixed shapes
constexpr int B = 32;
constexpr int C = 256;
constexpr int H = 64;
constexpr int HW = H * H;           // 4096 pixels
constexpr int N = 2048;             // anchors per batch
constexpr int CHUNK = 8;            // channels per CTA
constexpr int NCHUNKS = C / CHUNK;  // 32
constexpr int THREADS = 1024;       // 32 warps
constexpr size_t SMEM_BYTES = (size_t)HW * CHUNK * 4;  // 128 KB -> 1 CTA/SM

__device__ __forceinline__ float4 lerp4(float4 a, float4 b, float t) {
    return make_float4(fmaf(b.x - a.x, t, a.x),
                       fmaf(b.y - a.y, t, a.y),
                       fmaf(b.z - a.z, t, a.z),
                       fmaf(b.w - a.w, t, a.w));
}

__global__ __launch_bounds__(THREADS, 1)
void bilinear_gather_kernel(const float* __restrict__ fm,
                            const float* __restrict__ anchors,
                            float* __restrict__ out)
{
    // Two pixel-major planes: sA[p] = {c0..c3}, sB[p] = {c4..c7}.
    // Plane-separate so staging STS.128 (consecutive lanes -> consecutive
    // float4 slots) is natively conflict-free.
    extern __shared__ float4 smem[];
    float4* __restrict__ sA = smem;        // [4096]
    float4* __restrict__ sB = smem + HW;   // [4096]

    const int tid   = threadIdx.x;
    const int blk   = blockIdx.x;
    const int b     = blk >> 5;      // / NCHUNKS
    const int chunk = blk & 31;      // % NCHUNKS

    // ---- Stage + transpose to pixel-major.
    // Thread owns 4 pixels; 8 coalesced scalar LDG per pixel (stride-1 within
    // each channel plane across the warp) -> 2x STS.128, conflict-free.
    {
        const float* __restrict__ src =
            fm + ((size_t)b * C + (size_t)chunk * CHUNK) * HW;
        #pragma unroll
        for (int i = 0; i < HW / THREADS; ++i) {
            const int p = tid + i * THREADS;
            float4 a, c;
            a.x = src[0 * HW + p];
            a.y = src[1 * HW + p];
            a.z = src[2 * HW + p];
            a.w = src[3 * HW + p];
            c.x = src[4 * HW + p];
            c.y = src[5 * HW + p];
            c.z = src[6 * HW + p];
            c.w = src[7 * HW + p];
            sA[p] = a;
            sB[p] = c;
        }
    }
    __syncthreads();

    const float2* __restrict__ anc2 =
        reinterpret_cast<const float2*>(anchors + (size_t)b * N * 2);
    float* __restrict__ outb = out + (size_t)b * N * C + (size_t)chunk * CHUNK;

    // ---- Gather: one thread per anchor (math once per anchor),
    // 8x LDS.128 per anchor, 32B contiguous output per anchor (2x STG.128).
    #pragma unroll
    for (int j = 0; j < N / THREADS; ++j) {
        const int n = tid + j * THREADS;

        float2 a = anc2[n];
        float px = fminf(fmaxf(a.x * 63.0f, 0.0f), 63.0f);
        float py = fminf(fmaxf(a.y * 63.0f, 0.0f), 63.0f);

        float fx = floorf(px), fy = floorf(py);
        float cx = ceilf(px),  cy = ceilf(py);   // matches reference (rb==lt when integral)
        int xl = (int)fx, yl = (int)fy;
        int xr = (int)cx, yr = (int)cy;
        float dx = px - fx;
        float dy = py - fy;

        const int i_lt = yl * H + xl;
        const int i_rt = yl * H + xr;
        const int i_lb = yr * H + xl;
        const int i_rb = yr * H + xr;

        float4* __restrict__ o4 = reinterpret_cast<float4*>(outb + (size_t)n * C);

        // Plane A (channels 0..3)
        {
            float4 vlt = sA[i_lt];
            float4 vrt = sA[i_rt];
            float4 vlb = sA[i_lb];
            float4 vrb = sA[i_rb];
            float4 vt = lerp4(vlt, vrt, dx);
            float4 vb = lerp4(vlb, vrb, dx);
            o4[0] = lerp4(vt, vb, dy);
        }
        // Plane B (channels 4..7)
        {
            float4 vlt = sB[i_lt];
            float4 vrt = sB[i_rt];
            float4 vlb = sB[i_lb];
            float4 vrb = sB[i_rb];
            float4 vt = lerp4(vlt, vrt, dx);
            float4 vb = lerp4(vlb, vrb, dx);
            o4[1] = lerp4(vt, vb, dy);
        }
    }
}

extern "C" void kernel_launch(void* const* d_in, const int* in_sizes, int n_in,
                              void* d_out, int out_size)
{
    const float* fm      = (const float*)d_in[0];  // (32,256,64,64) fp32
    const float* anchors = (const float*)d_in[1];  // (32,2048,2) fp32
    float* out           = (float*)d_out;          // (32,2048,256) fp32

    cudaFuncSetAttribute(bilinear_gather_kernel,
                         cudaFuncAttributeMaxDynamicSharedMemorySize,
                         (int)SMEM_BYTES);

    dim3 grid(B * NCHUNKS);   // 256 CTAs
    dim3 block(THREADS);
    bilinear_gather_kernel<<<grid, block, SMEM_BYTES>>>(fm, anchors, out);
}